// round 12
// baseline (speedup 1.0000x reference)
#include <cuda_runtime.h>

#define NNAT 16
#define MAX_TILES 200000

// Per-tile packed accumulator written by k_hist piece blocks:
//   bits [42:64) = piece count
//   bits [0:42)  = sum over pieces of (q[nation]+pb+4.0) in fixed point, scale 2^30
// INVARIANT: zero outside a kernel_launch invocation (k_tiles restores zeros).
__device__ unsigned long long g_tcu[MAX_TILES];
// [0,64): sum tile_pos; [64,128): sum count_t*pte; [128,144): nation totals; [144,146): terrain counts
__device__ float g_acc[160];
__device__ float g_u[64];          // W_tile_top @ policy_w
__device__ float g_v[64];          // W_piece_bot @ policy_w
__device__ float g_terrsc[2];      // (terrain_emb @ W_tile_bot) @ policy_w
__device__ float g_nproj[16 * 64]; // nation_emb @ W_piece_top
__device__ float g_tproj[2 * 64];  // terrain_emb @ W_tile_bot
__device__ float g_c0;             // (tile_fc_b + nation_emb[active]) . w + policy_b
__device__ unsigned int g_done;    // last-block epilogue counter (reset by epilogue)

#define QSCALE 1073741824.0f   // 2^30
#define QOFF   4.0f
#define CNT_SHIFT 42
#define PARAM_BLOCKS 17
#define PPT 8                  // pieces per thread in hist blocks

// Fused: blocks 0..15 fold nproj row n; block 16 folds u/v/tproj/terrsc/c0
// (consumed by k_tiles next launch). Blocks >= 17 are piece-histogram blocks;
// they self-compute the packed per-nation increment table (q via the vtop
// factorization), so they don't depend on the param blocks.
__global__ void k_hist(const int* __restrict__ nation_idxs,
                       const int* __restrict__ piece_tile_idxs,
                       int P,
                       const float* __restrict__ tile_fc_w,
                       const float* __restrict__ tile_fc_b,
                       const float* __restrict__ piece_fc_w,
                       const float* __restrict__ piece_fc_b,
                       const float* __restrict__ tile_policy_w,
                       const float* __restrict__ tile_policy_b,
                       const float* __restrict__ nation_emb,
                       const float* __restrict__ terrain_emb,
                       const int*   __restrict__ active_nation)
{
    __shared__ float w[64];
    int tid = threadIdx.x;
    int b = blockIdx.x;

    if (b < PARAM_BLOCKS) {
        __shared__ float rA[64], rB[64], rD[64];
        if (tid < 64) w[tid] = tile_policy_w[tid];
        __syncthreads();

        if (b < 16) {
            // nproj[b][j] = sum_k nation_emb[b][k] * piece_fc_w[k][j]
            if (tid < 64) {
                float s = 0.f;
                #pragma unroll 16
                for (int k = 0; k < 64; k++)
                    s += nation_emb[b * 64 + k] * piece_fc_w[k * 64 + tid];
                g_nproj[b * 64 + tid] = s;
            }
        } else {
            if (tid < 64) {
                float su = 0.f, sv = 0.f, t0 = 0.f, t1 = 0.f;
                #pragma unroll 16
                for (int c = 0; c < 64; c++) {
                    su += tile_fc_w[tid * 64 + c] * w[c];          // u[j]
                    sv += piece_fc_w[(64 + tid) * 64 + c] * w[c];  // v[j]
                }
                #pragma unroll 16
                for (int k = 0; k < 64; k++) {
                    float tw = tile_fc_w[(64 + k) * 64 + tid];
                    t0 += terrain_emb[k] * tw;                     // tproj[0][j]
                    t1 += terrain_emb[64 + k] * tw;                // tproj[1][j]
                }
                g_u[tid] = su;
                g_v[tid] = sv;
                g_tproj[tid] = t0;
                g_tproj[64 + tid] = t1;

                int an = active_nation[0];
                rA[tid] = t0 * w[tid];
                rB[tid] = t1 * w[tid];
                rD[tid] = (tile_fc_b[tid] + nation_emb[an * 64 + tid]) * w[tid];
            }
            __syncthreads();
            if (tid < 3) {
                const float* r = (tid == 0) ? rA : (tid == 1) ? rB : rD;
                float s = 0.f;
                #pragma unroll 16
                for (int k = 0; k < 64; k++) s += r[k];
                if (tid == 0) g_terrsc[0] = s;
                else if (tid == 1) g_terrsc[1] = s;
                else g_c0 = s + tile_policy_b[0];
            }
        }
        return;
    }

    // ---- piece-histogram blocks (PPT pieces per thread) ----
    __shared__ float vtop[64], rP[64];
    __shared__ unsigned long long sq[NNAT];
    __shared__ unsigned int sh[NNAT];

    if (tid < 64) w[tid] = tile_policy_w[tid];
    __syncthreads();

    if (tid < 64) {
        // vtop[k] = piece_fc_w row k (W_piece_top) . w
        const float4* pr = reinterpret_cast<const float4*>(piece_fc_w + tid * 64);
        float s = 0.f;
        #pragma unroll
        for (int c = 0; c < 16; c++) {
            float4 p = pr[c];
            s += p.x * w[4 * c] + p.y * w[4 * c + 1]
               + p.z * w[4 * c + 2] + p.w * w[4 * c + 3];
        }
        vtop[tid] = s;
    } else if (tid < 128) {
        rP[tid - 64] = piece_fc_b[tid - 64] * w[tid - 64];
    }
    __syncthreads();

    if (tid < NNAT) {
        float pb = 0.f;
        #pragma unroll 16
        for (int j = 0; j < 64; j++) pb += rP[j];
        float q = 0.f;
        #pragma unroll 16
        for (int k = 0; k < 64; k++) q += nation_emb[tid * 64 + k] * vtop[k];
        sq[tid] = (unsigned long long)llroundf((q + pb + QOFF) * QSCALE)
                + (1ULL << CNT_SHIFT);
        sh[tid] = 0u;
    }
    __syncthreads();

    int i = (b - PARAM_BLOCKS) * blockDim.x + tid;   // index of PPT-piece group
    int Pg = P / PPT;
    if (i < Pg) {
        #pragma unroll
        for (int r = 0; r < PPT / 4; r++) {
            int4 n4 = reinterpret_cast<const int4*>(nation_idxs)[i * (PPT / 4) + r];
            int4 t4 = reinterpret_cast<const int4*>(piece_tile_idxs)[i * (PPT / 4) + r];
            atomicAdd(&g_tcu[t4.x], sq[n4.x]);
            atomicAdd(&g_tcu[t4.y], sq[n4.y]);
            atomicAdd(&g_tcu[t4.z], sq[n4.z]);
            atomicAdd(&g_tcu[t4.w], sq[n4.w]);
            atomicAdd(&sh[n4.x], 1u); atomicAdd(&sh[n4.y], 1u);
            atomicAdd(&sh[n4.z], 1u); atomicAdd(&sh[n4.w], 1u);
        }
    }
    int rem = P - Pg * PPT;
    if (i < rem) {
        int idx = Pg * PPT + i;
        atomicAdd(&g_tcu[piece_tile_idxs[idx]], sq[nation_idxs[idx]]);
        atomicAdd(&sh[nation_idxs[idx]], 1u);
    }
    __syncthreads();
    if (tid < NNAT) atomicAdd(&g_acc[128 + tid], (float)sh[tid]);
}

// Warp-per-tile, U=4 unroll; two 5-level butterflies per tile.
// Self-cleaning: zeroes g_tcu entries after consuming them.
// Last block to finish runs the pooled/value epilogue inline and zeroes g_acc/g_done.
__global__ void __launch_bounds__(256, 4)
k_tiles(const int*   __restrict__ tile_idxs,
        const int*   __restrict__ terrain,
        const float* __restrict__ tile_pos_emb,
        const float* __restrict__ piece_tile_emb,
        float*       __restrict__ out,
        int T, int P,
        const float* __restrict__ tile_fc_w,
        const float* __restrict__ tile_fc_b,
        const float* __restrict__ piece_fc_w,
        const float* __restrict__ piece_fc_b,
        const float* __restrict__ nation_emb,
        const int*   __restrict__ active_nation,
        const float* __restrict__ value_w1,
        const float* __restrict__ value_b1,
        const float* __restrict__ value_w2,
        const float* __restrict__ value_b2,
        const float* __restrict__ end_turn_logit)
{
    const int U = 4;
    int lane = threadIdx.x & 31;
    int gwid = (blockIdx.x * blockDim.x + threadIdx.x) >> 5;
    int nw   = (gridDim.x * blockDim.x) >> 5;

    float u0 = g_u[2 * lane], u1 = g_u[2 * lane + 1];
    float v0 = g_v[2 * lane], v1 = g_v[2 * lane + 1];
    float c0 = g_c0;
    float tsc0 = g_terrsc[0], tsc1 = g_terrsc[1];

    float ap0 = 0.f, ap1 = 0.f;   // sum tile_pos (this lane's 2 dims)
    float ac0 = 0.f, ac1 = 0.f;   // sum count_t * pte
    float tcc0 = 0.f, tcc1 = 0.f; // terrain counts (lane 0)

    const float2* __restrict__ tp_base = reinterpret_cast<const float2*>(tile_pos_emb);
    const float2* __restrict__ pe_base = reinterpret_cast<const float2*>(piece_tile_emb);

    for (int base = gwid * U; base < T; base += nw * U) {
        float2 tp[U], pe[U];
        float  cnt[U], qs[U];
        bool   val[U];

        #pragma unroll
        for (int i = 0; i < U; i++) {
            int t = base + i;
            val[i] = (t < T);
            int tt = val[i] ? t : base;
            int row = tile_idxs[tt];
            tp[i] = tp_base[row * 32 + lane];
            pe[i] = pe_base[tt * 32 + lane];
            unsigned long long pk = val[i] ? g_tcu[tt] : 0ull;  // broadcast 8B
            cnt[i] = (float)(unsigned int)(pk >> CNT_SHIFT);
            qs[i]  = (float)(long long)(pk & ((1ULL << CNT_SHIFT) - 1ull))
                     * (1.0f / QSCALE) - cnt[i] * QOFF;
        }
        #pragma unroll
        for (int i = 0; i < U; i++) {
            if (!val[i]) {
                tp[i] = make_float2(0.f, 0.f);
                pe[i] = make_float2(0.f, 0.f);
            }
        }

        // Restore zeros for the next graph replay (values already consumed).
        if (lane == 0) {
            #pragma unroll
            for (int i = 0; i < U; i++)
                if (val[i]) g_tcu[base + i] = 0ull;
        }

        float s1[U], s2[U];
        #pragma unroll
        for (int i = 0; i < U; i++) {
            s1[i] = tp[i].x * u0 + tp[i].y * u1;
            s2[i] = pe[i].x * v0 + pe[i].y * v1;
            ap0 += tp[i].x; ap1 += tp[i].y;
            ac0 += cnt[i] * pe[i].x; ac1 += cnt[i] * pe[i].y;
        }

        #pragma unroll
        for (int o = 16; o > 0; o >>= 1) {
            #pragma unroll
            for (int i = 0; i < U; i++) {
                s1[i] += __shfl_xor_sync(0xffffffffu, s1[i], o);
                s2[i] += __shfl_xor_sync(0xffffffffu, s2[i], o);
            }
        }

        if (lane == 0) {
            #pragma unroll
            for (int i = 0; i < U; i++) {
                if (val[i]) {
                    int t = base + i;
                    int e = terrain[t] - 1;
                    out[t] = s1[i] + (e == 0 ? tsc0 : tsc1)
                           + cnt[i] * s2[i] + qs[i] + c0;
                    if (e == 0) tcc0 += 1.f; else tcc1 += 1.f;
                }
            }
        }
    }

    atomicAdd(&g_acc[2 * lane],          ap0);
    atomicAdd(&g_acc[2 * lane + 1],      ap1);
    atomicAdd(&g_acc[64 + 2 * lane],     ac0);
    atomicAdd(&g_acc[64 + 2 * lane + 1], ac1);
    if (lane == 0) {
        atomicAdd(&g_acc[144], tcc0);
        atomicAdd(&g_acc[145], tcc1);
    }

    // ---- last-block epilogue (pooled mean -> value MLP) ----
    __threadfence();
    __syncthreads();
    __shared__ bool isLast;
    if (threadIdx.x == 0)
        isLast = (atomicAdd(&g_done, 1u) == gridDim.x - 1);
    __syncthreads();
    if (!isLast) return;

    __shared__ float part[4][64];
    __shared__ float pooled[64];
    __shared__ float h[64];
    int tid = threadIdx.x;
    int c = tid >> 6;       // k-chunk 0..3
    int j = tid & 63;       // output dim
    float fT = (float)T;

    float s = 0.f;
    #pragma unroll 16
    for (int k = c * 16; k < c * 16 + 16; k++) {
        s += g_acc[k]      * tile_fc_w[k * 64 + j];
        s += g_acc[64 + k] * piece_fc_w[(64 + k) * 64 + j];
    }
    #pragma unroll 4
    for (int n = c * 4; n < c * 4 + 4; n++)
        s += g_acc[128 + n] * g_nproj[n * 64 + j];
    if (c == 0) {
        s += g_acc[144] * g_tproj[j] + g_acc[145] * g_tproj[64 + j];
        int an_ = active_nation[0];
        s += fT * tile_fc_b[j] + (float)P * piece_fc_b[j]
           + fT * nation_emb[an_ * 64 + j];
    }
    part[c][j] = s;
    __syncthreads();

    // All g_acc reads are complete: restore zeros for the next replay.
    if (tid < 160) g_acc[tid] = 0.f;
    if (tid == 160) g_done = 0u;

    if (c == 0)
        pooled[j] = (part[0][j] + part[1][j] + part[2][j] + part[3][j]) / fT;
    __syncthreads();

    float hv = 0.f;
    #pragma unroll 16
    for (int k = c * 16; k < c * 16 + 16; k++)
        hv += pooled[k] * value_w1[k * 64 + j];
    part[c][j] = hv;
    __syncthreads();
    if (c == 0) {
        float x = part[0][j] + part[1][j] + part[2][j] + part[3][j] + value_b1[j];
        h[j] = x > 0.f ? x : 0.f;
    }
    __syncthreads();

    if (tid < 32) {
        float v = h[tid] * value_w2[tid] + h[tid + 32] * value_w2[tid + 32];
        #pragma unroll
        for (int o = 16; o > 0; o >>= 1)
            v += __shfl_xor_sync(0xffffffffu, v, o);
        if (tid == 0) {
            out[T]     = end_turn_logit[0];
            out[T + 1] = v + value_b2[0];
        }
    }
}

extern "C" void kernel_launch(void* const* d_in, const int* in_sizes, int n_in,
                              void* d_out, int out_size)
{
    const int*   tile_idxs      = (const int*)  d_in[0];
    const int*   terrain        = (const int*)  d_in[1];
    const int*   nation_idxs    = (const int*)  d_in[2];
    const int*   piece_tidx     = (const int*)  d_in[3];
    const int*   active         = (const int*)  d_in[4];
    const float* tile_pos_emb   = (const float*)d_in[5];
    const float* terrain_emb    = (const float*)d_in[6];
    const float* nation_emb     = (const float*)d_in[7];
    const float* piece_tile_emb = (const float*)d_in[8];
    const float* tile_fc_w      = (const float*)d_in[9];
    const float* tile_fc_b      = (const float*)d_in[10];
    const float* piece_fc_w     = (const float*)d_in[11];
    const float* piece_fc_b     = (const float*)d_in[12];
    const float* tile_policy_w  = (const float*)d_in[13];
    const float* tile_policy_b  = (const float*)d_in[14];
    const float* end_turn       = (const float*)d_in[15];
    const float* value_w1       = (const float*)d_in[16];
    const float* value_b1       = (const float*)d_in[17];
    const float* value_w2       = (const float*)d_in[18];
    const float* value_b2       = (const float*)d_in[19];
    float* out = (float*)d_out;

    int T = in_sizes[0];   // 200000
    int P = in_sizes[2];   // 1000000

    int piece_blocks = (P / PPT + 255) / 256;
    k_hist<<<PARAM_BLOCKS + piece_blocks, 256>>>(
        nation_idxs, piece_tidx, P,
        tile_fc_w, tile_fc_b, piece_fc_w, piece_fc_b,
        tile_policy_w, tile_policy_b, nation_emb, terrain_emb, active);

    k_tiles<<<592, 256>>>(tile_idxs, terrain, tile_pos_emb, piece_tile_emb, out,
                          T, P,
                          tile_fc_w, tile_fc_b, piece_fc_w, piece_fc_b,
                          nation_emb, active,
                          value_w1, value_b1, value_w2, value_b2, end_turn);
}

// round 14
// speedup vs baseline: 1.0113x; 1.0113x over previous
#include <cuda_runtime.h>

#define NNAT 16
#define MAX_TILES 200000

// Per-tile packed accumulator written by k_hist piece blocks:
//   bits [42:64) = piece count
//   bits [0:42)  = sum over pieces of (q[nation]+pb+4.0) in fixed point, scale 2^30
// INVARIANT: zero outside a kernel_launch invocation (k_tiles restores zeros).
__device__ unsigned long long g_tcu[MAX_TILES];
// [0,64): sum tile_pos; [64,128): sum count_t*pte; [128,144): nation totals; [144,146): terrain counts
__device__ float g_acc[160];
__device__ float g_u[64];          // W_tile_top @ policy_w
__device__ float g_v[64];          // W_piece_bot @ policy_w
__device__ float g_terrsc[2];      // (terrain_emb @ W_tile_bot) @ policy_w
__device__ float g_nproj[16 * 64]; // nation_emb @ W_piece_top
__device__ float g_tproj[2 * 64];  // terrain_emb @ W_tile_bot
__device__ float g_c0;             // (tile_fc_b + nation_emb[active]) . w + policy_b
__device__ unsigned int g_done;    // last-block epilogue counter (reset by epilogue)

#define QSCALE 1073741824.0f   // 2^30
#define QOFF   4.0f
#define CNT_SHIFT 42
#define PARAM_BLOCKS 17
#define PPT 8                  // pieces per thread in hist blocks

// Fused: blocks 0..15 fold nproj row n; block 16 folds u/v/tproj/terrsc/c0
// (consumed by k_tiles next launch). Blocks >= 17 are piece-histogram blocks;
// they self-compute the packed per-nation increment table (q via the vtop
// factorization), so they don't depend on the param blocks.
__global__ void k_hist(const int* __restrict__ nation_idxs,
                       const int* __restrict__ piece_tile_idxs,
                       int P,
                       const float* __restrict__ tile_fc_w,
                       const float* __restrict__ tile_fc_b,
                       const float* __restrict__ piece_fc_w,
                       const float* __restrict__ piece_fc_b,
                       const float* __restrict__ tile_policy_w,
                       const float* __restrict__ tile_policy_b,
                       const float* __restrict__ nation_emb,
                       const float* __restrict__ terrain_emb,
                       const int*   __restrict__ active_nation)
{
    __shared__ float w[64];
    int tid = threadIdx.x;
    int b = blockIdx.x;

    if (b < PARAM_BLOCKS) {
        __shared__ float rA[64], rB[64], rD[64];
        if (tid < 64) w[tid] = tile_policy_w[tid];
        __syncthreads();

        if (b < 16) {
            // nproj[b][j] = sum_k nation_emb[b][k] * piece_fc_w[k][j]
            if (tid < 64) {
                float s = 0.f;
                #pragma unroll 16
                for (int k = 0; k < 64; k++)
                    s += nation_emb[b * 64 + k] * piece_fc_w[k * 64 + tid];
                g_nproj[b * 64 + tid] = s;
            }
        } else {
            if (tid < 64) {
                float su = 0.f, sv = 0.f, t0 = 0.f, t1 = 0.f;
                #pragma unroll 16
                for (int c = 0; c < 64; c++) {
                    su += tile_fc_w[tid * 64 + c] * w[c];          // u[j]
                    sv += piece_fc_w[(64 + tid) * 64 + c] * w[c];  // v[j]
                }
                #pragma unroll 16
                for (int k = 0; k < 64; k++) {
                    float tw = tile_fc_w[(64 + k) * 64 + tid];
                    t0 += terrain_emb[k] * tw;                     // tproj[0][j]
                    t1 += terrain_emb[64 + k] * tw;                // tproj[1][j]
                }
                g_u[tid] = su;
                g_v[tid] = sv;
                g_tproj[tid] = t0;
                g_tproj[64 + tid] = t1;

                int an = active_nation[0];
                rA[tid] = t0 * w[tid];
                rB[tid] = t1 * w[tid];
                rD[tid] = (tile_fc_b[tid] + nation_emb[an * 64 + tid]) * w[tid];
            }
            __syncthreads();
            if (tid < 3) {
                const float* r = (tid == 0) ? rA : (tid == 1) ? rB : rD;
                float s = 0.f;
                #pragma unroll 16
                for (int k = 0; k < 64; k++) s += r[k];
                if (tid == 0) g_terrsc[0] = s;
                else if (tid == 1) g_terrsc[1] = s;
                else g_c0 = s + tile_policy_b[0];
            }
        }
        return;
    }

    // ---- piece-histogram blocks (PPT pieces per thread) ----
    __shared__ float vtop[64], rP[64];
    __shared__ unsigned long long sq[NNAT];
    __shared__ unsigned int sh[NNAT];

    if (tid < 64) w[tid] = tile_policy_w[tid];
    __syncthreads();

    if (tid < 64) {
        // vtop[k] = piece_fc_w row k (W_piece_top) . w
        const float4* pr = reinterpret_cast<const float4*>(piece_fc_w + tid * 64);
        float s = 0.f;
        #pragma unroll
        for (int c = 0; c < 16; c++) {
            float4 p = pr[c];
            s += p.x * w[4 * c] + p.y * w[4 * c + 1]
               + p.z * w[4 * c + 2] + p.w * w[4 * c + 3];
        }
        vtop[tid] = s;
    } else if (tid < 128) {
        rP[tid - 64] = piece_fc_b[tid - 64] * w[tid - 64];
    }
    __syncthreads();

    if (tid < NNAT) {
        float pb = 0.f;
        #pragma unroll 16
        for (int j = 0; j < 64; j++) pb += rP[j];
        float q = 0.f;
        #pragma unroll 16
        for (int k = 0; k < 64; k++) q += nation_emb[tid * 64 + k] * vtop[k];
        sq[tid] = (unsigned long long)llroundf((q + pb + QOFF) * QSCALE)
                + (1ULL << CNT_SHIFT);
        sh[tid] = 0u;
    }
    __syncthreads();

    int i = (b - PARAM_BLOCKS) * blockDim.x + tid;   // index of PPT-piece group
    int Pg = P / PPT;
    if (i < Pg) {
        #pragma unroll
        for (int r = 0; r < PPT / 4; r++) {
            int4 n4 = reinterpret_cast<const int4*>(nation_idxs)[i * (PPT / 4) + r];
            int4 t4 = reinterpret_cast<const int4*>(piece_tile_idxs)[i * (PPT / 4) + r];
            atomicAdd(&g_tcu[t4.x], sq[n4.x]);
            atomicAdd(&g_tcu[t4.y], sq[n4.y]);
            atomicAdd(&g_tcu[t4.z], sq[n4.z]);
            atomicAdd(&g_tcu[t4.w], sq[n4.w]);
            atomicAdd(&sh[n4.x], 1u); atomicAdd(&sh[n4.y], 1u);
            atomicAdd(&sh[n4.z], 1u); atomicAdd(&sh[n4.w], 1u);
        }
    }
    int rem = P - Pg * PPT;
    if (i < rem) {
        int idx = Pg * PPT + i;
        atomicAdd(&g_tcu[piece_tile_idxs[idx]], sq[nation_idxs[idx]]);
        atomicAdd(&sh[nation_idxs[idx]], 1u);
    }
    __syncthreads();
    if (tid < NNAT) atomicAdd(&g_acc[128 + tid], (float)sh[tid]);
}

// Warp-per-tile, U=6, SINGLE merged butterfly per tile (cnt is warp-uniform,
// so tp.u + cnt*(pe.v) reduces in one pass), with software-pipelined index
// prefetch to keep gathers flowing across iterations.
// Self-cleaning: zeroes g_tcu entries after consuming them.
// Last block to finish runs the pooled/value epilogue inline and zeroes g_acc/g_done.
__global__ void k_tiles(const int*   __restrict__ tile_idxs,
                        const int*   __restrict__ terrain,
                        const float* __restrict__ tile_pos_emb,
                        const float* __restrict__ piece_tile_emb,
                        float*       __restrict__ out,
                        int T, int P,
                        const float* __restrict__ tile_fc_w,
                        const float* __restrict__ tile_fc_b,
                        const float* __restrict__ piece_fc_w,
                        const float* __restrict__ piece_fc_b,
                        const float* __restrict__ nation_emb,
                        const int*   __restrict__ active_nation,
                        const float* __restrict__ value_w1,
                        const float* __restrict__ value_b1,
                        const float* __restrict__ value_w2,
                        const float* __restrict__ value_b2,
                        const float* __restrict__ end_turn_logit)
{
    const int U = 6;
    int lane = threadIdx.x & 31;
    int gwid = (blockIdx.x * blockDim.x + threadIdx.x) >> 5;
    int nw   = (gridDim.x * blockDim.x) >> 5;

    float u0 = g_u[2 * lane], u1 = g_u[2 * lane + 1];
    float v0 = g_v[2 * lane], v1 = g_v[2 * lane + 1];
    float c0 = g_c0;
    float tsc0 = g_terrsc[0], tsc1 = g_terrsc[1];

    float ap0 = 0.f, ap1 = 0.f;   // sum tile_pos (this lane's 2 dims)
    float ac0 = 0.f, ac1 = 0.f;   // sum count_t * pte
    float tcc0 = 0.f, tcc1 = 0.f; // terrain counts (lane 0)

    const float2* __restrict__ tp_base = reinterpret_cast<const float2*>(tile_pos_emb);
    const float2* __restrict__ pe_base = reinterpret_cast<const float2*>(piece_tile_emb);

    int nstep = nw * U;
    int base = gwid * U;

    // Prologue: prefetch first iteration's row indices.
    int idxc[U];
    #pragma unroll
    for (int i = 0; i < U; i++) {
        int t = base + i;
        idxc[i] = tile_idxs[(t < T) ? t : 0];
    }

    for (; base < T; base += nstep) {
        float2 tp[U], pe[U];
        float  cnt[U], qs[U];
        bool   val[U];

        #pragma unroll
        for (int i = 0; i < U; i++) {
            int t = base + i;
            val[i] = (t < T);
            int tt = val[i] ? t : 0;
            tp[i] = tp_base[idxc[i] * 32 + lane];
            pe[i] = pe_base[tt * 32 + lane];
            unsigned long long pk = val[i] ? g_tcu[tt] : 0ull;  // broadcast 8B
            cnt[i] = (float)(unsigned int)(pk >> CNT_SHIFT);
            qs[i]  = (float)(long long)(pk & ((1ULL << CNT_SHIFT) - 1ull))
                     * (1.0f / QSCALE) - cnt[i] * QOFF;
        }

        // Prefetch next iteration's row indices while gathers are in flight.
        int nbase = base + nstep;
        #pragma unroll
        for (int i = 0; i < U; i++) {
            int t = nbase + i;
            if (t < T) idxc[i] = tile_idxs[t];
        }

        // Restore zeros for the next graph replay (values already consumed).
        if (lane == 0) {
            #pragma unroll
            for (int i = 0; i < U; i++)
                if (val[i]) g_tcu[base + i] = 0ull;
        }

        float s[U];
        #pragma unroll
        for (int i = 0; i < U; i++) {
            if (!val[i]) {
                tp[i] = make_float2(0.f, 0.f);
                pe[i] = make_float2(0.f, 0.f);
            }
            s[i] = tp[i].x * u0 + tp[i].y * u1
                 + cnt[i] * (pe[i].x * v0 + pe[i].y * v1);
            ap0 += tp[i].x; ap1 += tp[i].y;
            ac0 += cnt[i] * pe[i].x; ac1 += cnt[i] * pe[i].y;
        }

        // Single merged butterfly: 5 levels x U independent shuffles.
        #pragma unroll
        for (int o = 16; o > 0; o >>= 1) {
            #pragma unroll
            for (int i = 0; i < U; i++)
                s[i] += __shfl_xor_sync(0xffffffffu, s[i], o);
        }

        if (lane == 0) {
            #pragma unroll
            for (int i = 0; i < U; i++) {
                if (val[i]) {
                    int t = base + i;
                    int e = terrain[t] - 1;
                    out[t] = s[i] + (e == 0 ? tsc0 : tsc1) + qs[i] + c0;
                    if (e == 0) tcc0 += 1.f; else tcc1 += 1.f;
                }
            }
        }
    }

    atomicAdd(&g_acc[2 * lane],          ap0);
    atomicAdd(&g_acc[2 * lane + 1],      ap1);
    atomicAdd(&g_acc[64 + 2 * lane],     ac0);
    atomicAdd(&g_acc[64 + 2 * lane + 1], ac1);
    if (lane == 0) {
        atomicAdd(&g_acc[144], tcc0);
        atomicAdd(&g_acc[145], tcc1);
    }

    // ---- last-block epilogue (pooled mean -> value MLP) ----
    __threadfence();
    __syncthreads();
    __shared__ bool isLast;
    if (threadIdx.x == 0)
        isLast = (atomicAdd(&g_done, 1u) == gridDim.x - 1);
    __syncthreads();
    if (!isLast) return;

    __shared__ float part[4][64];
    __shared__ float pooled[64];
    __shared__ float h[64];
    int tid = threadIdx.x;
    int c = tid >> 6;       // k-chunk 0..3
    int j = tid & 63;       // output dim
    float fT = (float)T;

    float s = 0.f;
    #pragma unroll 16
    for (int k = c * 16; k < c * 16 + 16; k++) {
        s += g_acc[k]      * tile_fc_w[k * 64 + j];
        s += g_acc[64 + k] * piece_fc_w[(64 + k) * 64 + j];
    }
    #pragma unroll 4
    for (int n = c * 4; n < c * 4 + 4; n++)
        s += g_acc[128 + n] * g_nproj[n * 64 + j];
    if (c == 0) {
        s += g_acc[144] * g_tproj[j] + g_acc[145] * g_tproj[64 + j];
        int an_ = active_nation[0];
        s += fT * tile_fc_b[j] + (float)P * piece_fc_b[j]
           + fT * nation_emb[an_ * 64 + j];
    }
    part[c][j] = s;
    __syncthreads();

    // All g_acc reads are complete: restore zeros for the next replay.
    if (tid < 160) g_acc[tid] = 0.f;
    if (tid == 160) g_done = 0u;

    if (c == 0)
        pooled[j] = (part[0][j] + part[1][j] + part[2][j] + part[3][j]) / fT;
    __syncthreads();

    float hv = 0.f;
    #pragma unroll 16
    for (int k = c * 16; k < c * 16 + 16; k++)
        hv += pooled[k] * value_w1[k * 64 + j];
    part[c][j] = hv;
    __syncthreads();
    if (c == 0) {
        float x = part[0][j] + part[1][j] + part[2][j] + part[3][j] + value_b1[j];
        h[j] = x > 0.f ? x : 0.f;
    }
    __syncthreads();

    if (tid < 32) {
        float v = h[tid] * value_w2[tid] + h[tid + 32] * value_w2[tid + 32];
        #pragma unroll
        for (int o = 16; o > 0; o >>= 1)
            v += __shfl_xor_sync(0xffffffffu, v, o);
        if (tid == 0) {
            out[T]     = end_turn_logit[0];
            out[T + 1] = v + value_b2[0];
        }
    }
}

extern "C" void kernel_launch(void* const* d_in, const int* in_sizes, int n_in,
                              void* d_out, int out_size)
{
    const int*   tile_idxs      = (const int*)  d_in[0];
    const int*   terrain        = (const int*)  d_in[1];
    const int*   nation_idxs    = (const int*)  d_in[2];
    const int*   piece_tidx     = (const int*)  d_in[3];
    const int*   active         = (const int*)  d_in[4];
    const float* tile_pos_emb   = (const float*)d_in[5];
    const float* terrain_emb    = (const float*)d_in[6];
    const float* nation_emb     = (const float*)d_in[7];
    const float* piece_tile_emb = (const float*)d_in[8];
    const float* tile_fc_w      = (const float*)d_in[9];
    const float* tile_fc_b      = (const float*)d_in[10];
    const float* piece_fc_w     = (const float*)d_in[11];
    const float* piece_fc_b     = (const float*)d_in[12];
    const float* tile_policy_w  = (const float*)d_in[13];
    const float* tile_policy_b  = (const float*)d_in[14];
    const float* end_turn       = (const float*)d_in[15];
    const float* value_w1       = (const float*)d_in[16];
    const float* value_b1       = (const float*)d_in[17];
    const float* value_w2       = (const float*)d_in[18];
    const float* value_b2       = (const float*)d_in[19];
    float* out = (float*)d_out;

    int T = in_sizes[0];   // 200000
    int P = in_sizes[2];   // 1000000

    int piece_blocks = (P / PPT + 255) / 256;
    k_hist<<<PARAM_BLOCKS + piece_blocks, 256>>>(
        nation_idxs, piece_tidx, P,
        tile_fc_w, tile_fc_b, piece_fc_w, piece_fc_b,
        tile_policy_w, tile_policy_b, nation_emb, terrain_emb, active);

    k_tiles<<<592, 256>>>(tile_idxs, terrain, tile_pos_emb, piece_tile_emb, out,
                          T, P,
                          tile_fc_w, tile_fc_b, piece_fc_w, piece_fc_b,
                          nation_emb, active,
                          value_w1, value_b1, value_w2, value_b2, end_turn);
}